// round 5
// baseline (speedup 1.0000x reference)
#include <cuda_runtime.h>
#include <cuda_bf16.h>

#define Nn  8
#define Cc  64
#define Hh  128
#define Ww  512
#define CoN 64
#define HW  (Hh * Ww)      // 65536
#define NOFF 18
#define SSTR 68            // deform sample tile stride (floats): 272B, 16B-aligned,
                           // conflict-free fragment reads (68*gr+tc covers 32 banks)
#define XSTR 136           // offset-conv x-tile stride

// Scratch: offsets, NHWC transposed input, tf32 B-fragment tables.
__device__ float  g_off[(size_t)Nn * NOFF * HW];       // ~36 MB
__device__ float  g_xt[(size_t)Nn * HW * Cc];          // ~134 MB  [n][y][x][c]
__device__ float2 g_wfrag[9 * 8 * 8 * 32];             // deform B frags
__device__ float2 g_wofrag[72 * 3 * 32];               // offset B frags

__device__ __forceinline__ unsigned f2tf32(float v) {
    unsigned u;
    asm("cvt.rna.tf32.f32 %0, %1;" : "=r"(u) : "f"(v));
    return u;
}

// ---------------------------------------------------------------------------
// Kernel T: NCHW -> NHWC transpose of x. Block 32x8, 32x-by-32c smem tile.
// ---------------------------------------------------------------------------
__global__ void __launch_bounds__(256) nhwc_kernel(const float* __restrict__ x) {
    __shared__ float tile[32][33];
    int n = blockIdx.z / Hh;
    int y = blockIdx.z % Hh;
    int x0 = blockIdx.x * 32;
    int c0 = blockIdx.y * 32;

    const float* src = x + ((size_t)n * Cc + c0) * HW + (size_t)y * Ww + x0;
#pragma unroll
    for (int cc = threadIdx.y; cc < 32; cc += 8)
        tile[cc][threadIdx.x] = src[(size_t)cc * HW + threadIdx.x];
    __syncthreads();

    float* dst = g_xt + ((size_t)blockIdx.z * Ww + x0) * Cc + c0;
#pragma unroll
    for (int xx = threadIdx.y; xx < 32; xx += 8)
        dst[(size_t)xx * Cc + threadIdx.x] = tile[threadIdx.x][xx];
}

// ---------------------------------------------------------------------------
// Kernel 0a: deform B fragments (m16n8k8 tf32).
// ---------------------------------------------------------------------------
__global__ void wfrag_kernel(const float* __restrict__ wdef) {
    int idx = blockIdx.x * 256 + threadIdx.x;
    if (idx >= 9 * 8 * 8 * 32) return;
    int lane = idx & 31;
    int ni   = (idx >> 5) & 7;
    int k    = (idx >> 8) & 7;
    int t    = idx >> 11;
    int c = 8 * k + (lane & 3);
    int o = 8 * ni + (lane >> 2);
    float b0 = wdef[(o * 64 + c) * 9 + t];
    float b1 = wdef[(o * 64 + c + 4) * 9 + t];
    g_wfrag[idx] = make_float2(__uint_as_float(f2tf32(b0)),
                               __uint_as_float(f2tf32(b1)));
}

// ---------------------------------------------------------------------------
// Kernel 0b: offset-conv B fragments (oc padded 18 -> 24).
// ---------------------------------------------------------------------------
__global__ void wofrag_kernel(const float* __restrict__ woff) {
    int idx = blockIdx.x * 256 + threadIdx.x;
    if (idx >= 72 * 3 * 32) return;
    int lane = idx & 31;
    int rem  = idx >> 5;
    int ni   = rem % 3;
    int ks   = rem / 3;
    int gr = lane >> 2, tc = lane & 3;
    int k0 = 8 * ks + tc;
    int oc = 8 * ni + gr;
    float b0 = (oc < 18) ? woff[oc * 576 + k0]     : 0.0f;
    float b1 = (oc < 18) ? woff[oc * 576 + k0 + 4] : 0.0f;
    g_wofrag[(ks * 3 + ni) * 32 + lane] =
        make_float2(__uint_as_float(f2tf32(b0)), __uint_as_float(f2tf32(b1)));
}

// ---------------------------------------------------------------------------
// Kernel 1: offset conv via tf32 MMA (unchanged from Round 4).
// ---------------------------------------------------------------------------
__global__ void __launch_bounds__(128) offset_mma_kernel(
    const float* __restrict__ xin,
    const float* __restrict__ boff)
{
    __shared__ float sx[24 * XSTR];

    int tid  = threadIdx.x;
    int lane = tid & 31;
    int warp = tid >> 5;
    int gr   = lane >> 2;
    int tc   = lane & 3;

    int x0 = blockIdx.x * 128;
    int y  = blockIdx.y;
    int n  = blockIdx.z;

    float acc[2][3][4];
#pragma unroll
    for (int ni = 0; ni < 3; ni++) {
        int oc = 8 * ni + 2 * tc;
        float blo = (oc < 18)     ? __ldg(&boff[oc])     : 0.0f;
        float bhi = (oc + 1 < 18) ? __ldg(&boff[oc + 1]) : 0.0f;
#pragma unroll
        for (int mi = 0; mi < 2; mi++) {
            acc[mi][ni][0] = blo; acc[mi][ni][1] = bhi;
            acc[mi][ni][2] = blo; acc[mi][ni][3] = bhi;
        }
    }

    const float* xb = xin + (size_t)n * Cc * HW;

    for (int ch = 0; ch < 8; ch++) {
        __syncthreads();
        for (int idx = tid; idx < 3120; idx += 128) {
            int c   = idx / 390;
            int r   = idx - 390 * c;
            int i   = r / 130;
            int col = r - 130 * i;
            int yy = y + i - 1;
            int xx = x0 + col - 1;
            float v = 0.0f;
            if (yy >= 0 && yy < Hh && xx >= 0 && xx < Ww)
                v = xb[(size_t)(ch * 8 + c) * HW + yy * Ww + xx];
            sx[(c * 3 + i) * XSTR + col] = __uint_as_float(f2tf32(v));
        }
        __syncthreads();

#pragma unroll
        for (int kk = 0; kk < 9; kk++) {
            int kl = 8 * kk + tc;
            int c0 = kl / 9,  t0 = kl - 9 * c0;
            int i0 = t0 / 3,  j0 = t0 - 3 * i0;
            int kl2 = kl + 4;
            int c1 = kl2 / 9, t1 = kl2 - 9 * c1;
            int i1 = t1 / 3,  j1 = t1 - 3 * i1;
            int off0 = (c0 * 3 + i0) * XSTR + j0;
            int off1 = (c1 * 3 + i1) * XSTR + j1;

            const float2* wf = g_wofrag + (size_t)(ch * 9 + kk) * 96;
            float2 bfr[3];
#pragma unroll
            for (int ni = 0; ni < 3; ni++) bfr[ni] = __ldg(&wf[ni * 32 + lane]);

#pragma unroll
            for (int mi = 0; mi < 2; mi++) {
                int m = warp * 32 + mi * 16 + gr;
                unsigned a0 = __float_as_uint(sx[off0 + m]);
                unsigned a1 = __float_as_uint(sx[off0 + m + 8]);
                unsigned a2 = __float_as_uint(sx[off1 + m]);
                unsigned a3 = __float_as_uint(sx[off1 + m + 8]);
#pragma unroll
                for (int ni = 0; ni < 3; ni++) {
                    unsigned b0 = __float_as_uint(bfr[ni].x);
                    unsigned b1 = __float_as_uint(bfr[ni].y);
                    asm volatile(
                        "mma.sync.aligned.m16n8k8.row.col.f32.tf32.tf32.f32 "
                        "{%0,%1,%2,%3}, {%4,%5,%6,%7}, {%8,%9}, {%0,%1,%2,%3};"
                        : "+f"(acc[mi][ni][0]), "+f"(acc[mi][ni][1]),
                          "+f"(acc[mi][ni][2]), "+f"(acc[mi][ni][3])
                        : "r"(a0), "r"(a1), "r"(a2), "r"(a3),
                          "r"(b0), "r"(b1));
                }
            }
        }
    }

    size_t ob = (size_t)n * NOFF * HW + (size_t)y * Ww + x0;
#pragma unroll
    for (int ni = 0; ni < 3; ni++) {
        int oc = 8 * ni + 2 * tc;
#pragma unroll
        for (int mi = 0; mi < 2; mi++) {
            int pr = warp * 32 + mi * 16 + gr;
            if (oc < 18) {
                g_off[ob + (size_t)oc * HW + pr]     = acc[mi][ni][0];
                g_off[ob + (size_t)oc * HW + pr + 8] = acc[mi][ni][2];
            }
            if (oc + 1 < 18) {
                g_off[ob + (size_t)(oc + 1) * HW + pr]     = acc[mi][ni][1];
                g_off[ob + (size_t)(oc + 1) * HW + pr + 8] = acc[mi][ni][3];
            }
        }
    }
}

// ---------------------------------------------------------------------------
// Kernel 2: deformable conv via tf32 MMA, NHWC vectorized gathers.
// Phase 1 per tap: each thread gathers 4 corner vectors (64 ch contiguous,
// float4) from g_xt, blends, stores STS.128 into the sample tile.
// ---------------------------------------------------------------------------
__global__ void __launch_bounds__(128) deform_mma_kernel(
    const float* __restrict__ bdef,
    float* __restrict__ out)
{
    __shared__ __align__(16) float sS[128 * SSTR];   // 34.8 KB

    int tid  = threadIdx.x;
    int lane = tid & 31;
    int warp = tid >> 5;
    int gr   = lane >> 2;
    int tc   = lane & 3;

    int x0 = blockIdx.x * 128;
    int y  = blockIdx.y;
    int n  = blockIdx.z;
    int xg = x0 + tid;

    float acc[2][8][4];
#pragma unroll
    for (int ni = 0; ni < 8; ni++) {
        float blo = __ldg(&bdef[8 * ni + 2 * tc]);
        float bhi = __ldg(&bdef[8 * ni + 2 * tc + 1]);
#pragma unroll
        for (int mi = 0; mi < 2; mi++) {
            acc[mi][ni][0] = blo; acc[mi][ni][1] = bhi;
            acc[mi][ni][2] = blo; acc[mi][ni][3] = bhi;
        }
    }

    const float* xb   = g_xt + (size_t)n * HW * Cc;
    const float* offb = g_off + (size_t)n * NOFF * HW + (size_t)y * Ww + xg;

    for (int t = 0; t < 9; t++) {
        float dy = offb[(size_t)(2 * t) * HW];
        float dx = offb[(size_t)(2 * t + 1) * HW];
        int i = t / 3, j = t % 3;
        float py = (float)(y + i - 1) + dy;
        float px = (float)(xg + j - 1) + dx;

        float fy = floorf(py), fx = floorf(px);
        float wy1 = py - fy, wx1 = px - fx;
        float wy0 = 1.0f - wy1, wx0 = 1.0f - wx1;
        int iy0 = (int)fy, ix0 = (int)fx;
        int iy1 = iy0 + 1, ix1 = ix0 + 1;

        float gy0 = (iy0 >= 0 && iy0 < Hh) ? wy0 : 0.0f;
        float gy1 = (iy1 >= 0 && iy1 < Hh) ? wy1 : 0.0f;
        float gx0 = (ix0 >= 0 && ix0 < Ww) ? wx0 : 0.0f;
        float gx1 = (ix1 >= 0 && ix1 < Ww) ? wx1 : 0.0f;
        float c00 = gy0 * gx0, c01 = gy0 * gx1;
        float c10 = gy1 * gx0, c11 = gy1 * gx1;

        int yc0 = min(max(iy0, 0), Hh - 1), yc1 = min(max(iy1, 0), Hh - 1);
        int xc0 = min(max(ix0, 0), Ww - 1), xc1 = min(max(ix1, 0), Ww - 1);
        const float4* p00 = (const float4*)(xb + ((size_t)(yc0 * Ww + xc0) << 6));
        const float4* p01 = (const float4*)(xb + ((size_t)(yc0 * Ww + xc1) << 6));
        const float4* p10 = (const float4*)(xb + ((size_t)(yc1 * Ww + xc0) << 6));
        const float4* p11 = (const float4*)(xb + ((size_t)(yc1 * Ww + xc1) << 6));

        __syncthreads();   // previous tap's MMA reads finished
        {
            float4* srow = (float4*)(sS + tid * SSTR);
#pragma unroll
            for (int q = 0; q < 16; q++) {
                float4 a = p00[q], b = p01[q], c = p10[q], d = p11[q];
                float4 v;
                v.x = fmaf(c11, d.x, fmaf(c10, c.x, fmaf(c01, b.x, c00 * a.x)));
                v.y = fmaf(c11, d.y, fmaf(c10, c.y, fmaf(c01, b.y, c00 * a.y)));
                v.z = fmaf(c11, d.z, fmaf(c10, c.z, fmaf(c01, b.z, c00 * a.z)));
                v.w = fmaf(c11, d.w, fmaf(c10, c.w, fmaf(c01, b.w, c00 * a.w)));
                v.x = __uint_as_float(f2tf32(v.x));
                v.y = __uint_as_float(f2tf32(v.y));
                v.z = __uint_as_float(f2tf32(v.z));
                v.w = __uint_as_float(f2tf32(v.w));
                srow[q] = v;
            }
        }
        __syncthreads();

        const float2* wf = g_wfrag + (size_t)t * 8 * 8 * 32;
#pragma unroll
        for (int k = 0; k < 8; k++) {
            unsigned a[2][4];
#pragma unroll
            for (int mi = 0; mi < 2; mi++) {
                const float* base = sS + (warp * 32 + mi * 16 + gr) * SSTR + 8 * k + tc;
                a[mi][0] = __float_as_uint(base[0]);
                a[mi][1] = __float_as_uint(base[8 * SSTR]);
                a[mi][2] = __float_as_uint(base[4]);
                a[mi][3] = __float_as_uint(base[8 * SSTR + 4]);
            }
#pragma unroll
            for (int ni = 0; ni < 8; ni++) {
                float2 b = __ldg(&wf[(k * 8 + ni) * 32 + lane]);
                unsigned b0 = __float_as_uint(b.x);
                unsigned b1 = __float_as_uint(b.y);
#pragma unroll
                for (int mi = 0; mi < 2; mi++) {
                    asm volatile(
                        "mma.sync.aligned.m16n8k8.row.col.f32.tf32.tf32.f32 "
                        "{%0,%1,%2,%3}, {%4,%5,%6,%7}, {%8,%9}, {%0,%1,%2,%3};"
                        : "+f"(acc[mi][ni][0]), "+f"(acc[mi][ni][1]),
                          "+f"(acc[mi][ni][2]), "+f"(acc[mi][ni][3])
                        : "r"(a[mi][0]), "r"(a[mi][1]), "r"(a[mi][2]), "r"(a[mi][3]),
                          "r"(b0), "r"(b1));
                }
            }
        }
    }

    size_t ob = (size_t)n * CoN * HW + (size_t)y * Ww + x0;
#pragma unroll
    for (int ni = 0; ni < 8; ni++) {
        int o = 8 * ni + 2 * tc;
#pragma unroll
        for (int mi = 0; mi < 2; mi++) {
            int pr = warp * 32 + mi * 16 + gr;
            out[ob + (size_t)o * HW + pr]           = acc[mi][ni][0];
            out[ob + (size_t)(o + 1) * HW + pr]     = acc[mi][ni][1];
            out[ob + (size_t)o * HW + pr + 8]       = acc[mi][ni][2];
            out[ob + (size_t)(o + 1) * HW + pr + 8] = acc[mi][ni][3];
        }
    }
}

// ---------------------------------------------------------------------------
extern "C" void kernel_launch(void* const* d_in, const int* in_sizes, int n_in,
                              void* d_out, int out_size)
{
    const float* x    = (const float*)d_in[0];
    const float* woff = (const float*)d_in[1];
    const float* boff = (const float*)d_in[2];
    const float* wdef = (const float*)d_in[3];
    const float* bdef = (const float*)d_in[4];
    float* out = (float*)d_out;

    wfrag_kernel<<<(9 * 8 * 8 * 32 + 255) / 256, 256>>>(wdef);
    wofrag_kernel<<<(72 * 3 * 32 + 255) / 256, 256>>>(woff);
    nhwc_kernel<<<dim3(Ww / 32, Cc / 32, Nn * Hh), dim3(32, 8)>>>(x);
    offset_mma_kernel<<<dim3(Ww / 128, Hh, Nn), 128>>>(x, boff);
    deform_mma_kernel<<<dim3(Ww / 128, Hh, Nn), 128>>>(bdef, out);
}

// round 6
// speedup vs baseline: 1.2854x; 1.2854x over previous
#include <cuda_runtime.h>
#include <cuda_bf16.h>

#define Nn  8
#define Cc  64
#define Hh  128
#define Ww  512
#define CoN 64
#define HW  (Hh * Ww)      // 65536
#define NOFF 18
#define SSTR 68            // deform tile stride (floats): 272B, 16B-aligned
#define XSTR 136           // offset-conv x-tile stride

// Scratch: offsets and tf32 B-fragment tables.
__device__ float  g_off[(size_t)Nn * NOFF * HW];   // ~36 MB
__device__ float2 g_wfrag[9 * 8 * 8 * 32];         // deform B frags
__device__ float2 g_wofrag[72 * 3 * 32];           // offset B frags

__device__ __forceinline__ unsigned f2tf32(float v) {
    unsigned u;
    asm("cvt.rna.tf32.f32 %0, %1;" : "=r"(u) : "f"(v));
    return u;
}

// ---------------------------------------------------------------------------
// Kernel 0a: deform B fragments (m16n8k8 tf32).
// ---------------------------------------------------------------------------
__global__ void wfrag_kernel(const float* __restrict__ wdef) {
    int idx = blockIdx.x * 256 + threadIdx.x;
    if (idx >= 9 * 8 * 8 * 32) return;
    int lane = idx & 31;
    int ni   = (idx >> 5) & 7;
    int k    = (idx >> 8) & 7;
    int t    = idx >> 11;
    int c = 8 * k + (lane & 3);
    int o = 8 * ni + (lane >> 2);
    float b0 = wdef[(o * 64 + c) * 9 + t];
    float b1 = wdef[(o * 64 + c + 4) * 9 + t];
    g_wfrag[idx] = make_float2(__uint_as_float(f2tf32(b0)),
                               __uint_as_float(f2tf32(b1)));
}

// ---------------------------------------------------------------------------
// Kernel 0b: offset-conv B fragments (oc padded 18 -> 24).
// ---------------------------------------------------------------------------
__global__ void wofrag_kernel(const float* __restrict__ woff) {
    int idx = blockIdx.x * 256 + threadIdx.x;
    if (idx >= 72 * 3 * 32) return;
    int lane = idx & 31;
    int rem  = idx >> 5;
    int ni   = rem % 3;
    int ks   = rem / 3;
    int gr = lane >> 2, tc = lane & 3;
    int k0 = 8 * ks + tc;
    int oc = 8 * ni + gr;
    float b0 = (oc < 18) ? woff[oc * 576 + k0]     : 0.0f;
    float b1 = (oc < 18) ? woff[oc * 576 + k0 + 4] : 0.0f;
    g_wofrag[(ks * 3 + ni) * 32 + lane] =
        make_float2(__uint_as_float(f2tf32(b0)), __uint_as_float(f2tf32(b1)));
}

// ---------------------------------------------------------------------------
// Kernel 1: offset conv via tf32 MMA. Fill loop restructured: fully unrolled
// over 24 (c,i) rows, col = tid (+ 2-thread tail) -> no integer div/mod.
// ---------------------------------------------------------------------------
__global__ void __launch_bounds__(128) offset_mma_kernel(
    const float* __restrict__ xin,
    const float* __restrict__ boff)
{
    __shared__ float sx[24 * XSTR];

    int tid  = threadIdx.x;
    int lane = tid & 31;
    int warp = tid >> 5;
    int gr   = lane >> 2;
    int tc   = lane & 3;

    int x0 = blockIdx.x * 128;
    int y  = blockIdx.y;
    int n  = blockIdx.z;

    float acc[2][3][4];
#pragma unroll
    for (int ni = 0; ni < 3; ni++) {
        int oc = 8 * ni + 2 * tc;
        float blo = (oc < 18)     ? __ldg(&boff[oc])     : 0.0f;
        float bhi = (oc + 1 < 18) ? __ldg(&boff[oc + 1]) : 0.0f;
#pragma unroll
        for (int mi = 0; mi < 2; mi++) {
            acc[mi][ni][0] = blo; acc[mi][ni][1] = bhi;
            acc[mi][ni][2] = blo; acc[mi][ni][3] = bhi;
        }
    }

    const float* xb = xin + (size_t)n * Cc * HW;
    // border predicates shared across rows
    int xxa = x0 + tid - 1;           // col = tid
    bool va  = (xxa >= 0 && xxa < Ww);
    int xxb = x0 + tid + 127;         // col = tid + 128 (only tid<2 used)
    bool vb  = (tid < 2) && (xxb < Ww);

    for (int ch = 0; ch < 8; ch++) {
        __syncthreads();
#pragma unroll
        for (int r = 0; r < 24; r++) {
            const int c = r / 3, i = r % 3;        // compile-time after unroll
            int yy = y + i - 1;
            bool vy = (yy >= 0 && yy < Hh);
            const float* src = xb + (size_t)(ch * 8 + c) * HW + yy * Ww;
            float v0 = (vy && va) ? src[xxa] : 0.0f;
            sx[r * XSTR + tid] = __uint_as_float(f2tf32(v0));
            if (tid < 2) {
                float v1 = (vy && vb) ? src[xxb] : 0.0f;
                sx[r * XSTR + 128 + tid] = __uint_as_float(f2tf32(v1));
            }
        }
        __syncthreads();

#pragma unroll
        for (int kk = 0; kk < 9; kk++) {
            int kl = 8 * kk + tc;
            int c0 = kl / 9,  t0 = kl - 9 * c0;
            int i0 = t0 / 3,  j0 = t0 - 3 * i0;
            int kl2 = kl + 4;
            int c1 = kl2 / 9, t1 = kl2 - 9 * c1;
            int i1 = t1 / 3,  j1 = t1 - 3 * i1;
            int off0 = (c0 * 3 + i0) * XSTR + j0;
            int off1 = (c1 * 3 + i1) * XSTR + j1;

            const float2* wf = g_wofrag + (size_t)(ch * 9 + kk) * 96;
            float2 bfr[3];
#pragma unroll
            for (int ni = 0; ni < 3; ni++) bfr[ni] = __ldg(&wf[ni * 32 + lane]);

#pragma unroll
            for (int mi = 0; mi < 2; mi++) {
                int m = warp * 32 + mi * 16 + gr;
                unsigned a0 = __float_as_uint(sx[off0 + m]);
                unsigned a1 = __float_as_uint(sx[off0 + m + 8]);
                unsigned a2 = __float_as_uint(sx[off1 + m]);
                unsigned a3 = __float_as_uint(sx[off1 + m + 8]);
#pragma unroll
                for (int ni = 0; ni < 3; ni++) {
                    unsigned b0 = __float_as_uint(bfr[ni].x);
                    unsigned b1 = __float_as_uint(bfr[ni].y);
                    asm volatile(
                        "mma.sync.aligned.m16n8k8.row.col.f32.tf32.tf32.f32 "
                        "{%0,%1,%2,%3}, {%4,%5,%6,%7}, {%8,%9}, {%0,%1,%2,%3};"
                        : "+f"(acc[mi][ni][0]), "+f"(acc[mi][ni][1]),
                          "+f"(acc[mi][ni][2]), "+f"(acc[mi][ni][3])
                        : "r"(a0), "r"(a1), "r"(a2), "r"(a3),
                          "r"(b0), "r"(b1));
                }
            }
        }
    }

    size_t ob = (size_t)n * NOFF * HW + (size_t)y * Ww + x0;
#pragma unroll
    for (int ni = 0; ni < 3; ni++) {
        int oc = 8 * ni + 2 * tc;
#pragma unroll
        for (int mi = 0; mi < 2; mi++) {
            int pr = warp * 32 + mi * 16 + gr;
            if (oc < 18) {
                g_off[ob + (size_t)oc * HW + pr]     = acc[mi][ni][0];
                g_off[ob + (size_t)oc * HW + pr + 8] = acc[mi][ni][2];
            }
            if (oc + 1 < 18) {
                g_off[ob + (size_t)(oc + 1) * HW + pr]     = acc[mi][ni][1];
                g_off[ob + (size_t)(oc + 1) * HW + pr + 8] = acc[mi][ni][3];
            }
        }
    }
}

// ---------------------------------------------------------------------------
// Kernel 2: deformable conv via tf32 MMA (Round-4 NCHW gather), but with
// warp-private tile synchronization: the 128x68 tile is disjoint per warp
// (thread tid writes row tid; warp w reads rows [32w,32w+32)), so CTA-wide
// __syncthreads() is replaced by __syncwarp() -> warps pipeline independently.
// ---------------------------------------------------------------------------
__global__ void __launch_bounds__(128) deform_mma_kernel(
    const float* __restrict__ xin,
    const float* __restrict__ bdef,
    float* __restrict__ out)
{
    __shared__ __align__(16) float sS[128 * SSTR];   // 34.8 KB, warp-private quarters

    int tid  = threadIdx.x;
    int lane = tid & 31;
    int warp = tid >> 5;
    int gr   = lane >> 2;
    int tc   = lane & 3;

    int x0 = blockIdx.x * 128;
    int y  = blockIdx.y;
    int n  = blockIdx.z;
    int xg = x0 + tid;

    float acc[2][8][4];
#pragma unroll
    for (int ni = 0; ni < 8; ni++) {
        float blo = __ldg(&bdef[8 * ni + 2 * tc]);
        float bhi = __ldg(&bdef[8 * ni + 2 * tc + 1]);
#pragma unroll
        for (int mi = 0; mi < 2; mi++) {
            acc[mi][ni][0] = blo; acc[mi][ni][1] = bhi;
            acc[mi][ni][2] = blo; acc[mi][ni][3] = bhi;
        }
    }

    const float* xb   = xin + (size_t)n * Cc * HW;
    const float* offb = g_off + (size_t)n * NOFF * HW + (size_t)y * Ww + xg;

    for (int t = 0; t < 9; t++) {
        float dy = offb[(size_t)(2 * t) * HW];
        float dx = offb[(size_t)(2 * t + 1) * HW];
        int i = t / 3, j = t % 3;
        float py = (float)(y + i - 1) + dy;
        float px = (float)(xg + j - 1) + dx;

        float fy = floorf(py), fx = floorf(px);
        float wy1 = py - fy, wx1 = px - fx;
        float wy0 = 1.0f - wy1, wx0 = 1.0f - wx1;
        int iy0 = (int)fy, ix0 = (int)fx;
        int iy1 = iy0 + 1, ix1 = ix0 + 1;

        float gy0 = (iy0 >= 0 && iy0 < Hh) ? wy0 : 0.0f;
        float gy1 = (iy1 >= 0 && iy1 < Hh) ? wy1 : 0.0f;
        float gx0 = (ix0 >= 0 && ix0 < Ww) ? wx0 : 0.0f;
        float gx1 = (ix1 >= 0 && ix1 < Ww) ? wx1 : 0.0f;
        float c00 = gy0 * gx0, c01 = gy0 * gx1;
        float c10 = gy1 * gx0, c11 = gy1 * gx1;

        int yc0 = min(max(iy0, 0), Hh - 1), yc1 = min(max(iy1, 0), Hh - 1);
        int xc0 = min(max(ix0, 0), Ww - 1), xc1 = min(max(ix1, 0), Ww - 1);
        int o00 = yc0 * Ww + xc0, o01 = yc0 * Ww + xc1;
        int o10 = yc1 * Ww + xc0, o11 = yc1 * Ww + xc1;

        __syncwarp();   // this warp's previous-tap MMA reads are done
        {
            float* srow = sS + tid * SSTR;
            const float* p = xb;
#pragma unroll 4
            for (int c = 0; c < Cc; c++) {
                float v;
                v = c00 * p[o00];
                v = fmaf(c01, p[o01], v);
                v = fmaf(c10, p[o10], v);
                v = fmaf(c11, p[o11], v);
                srow[c] = __uint_as_float(f2tf32(v));
                p += HW;
            }
        }
        __syncwarp();   // tile rows for this warp visible

        const float2* wf = g_wfrag + (size_t)t * 8 * 8 * 32;
#pragma unroll
        for (int k = 0; k < 8; k++) {
            unsigned a[2][4];
#pragma unroll
            for (int mi = 0; mi < 2; mi++) {
                const float* base = sS + (warp * 32 + mi * 16 + gr) * SSTR + 8 * k + tc;
                a[mi][0] = __float_as_uint(base[0]);
                a[mi][1] = __float_as_uint(base[8 * SSTR]);
                a[mi][2] = __float_as_uint(base[4]);
                a[mi][3] = __float_as_uint(base[8 * SSTR + 4]);
            }
#pragma unroll
            for (int ni = 0; ni < 8; ni++) {
                float2 b = __ldg(&wf[(k * 8 + ni) * 32 + lane]);
                unsigned b0 = __float_as_uint(b.x);
                unsigned b1 = __float_as_uint(b.y);
#pragma unroll
                for (int mi = 0; mi < 2; mi++) {
                    asm volatile(
                        "mma.sync.aligned.m16n8k8.row.col.f32.tf32.tf32.f32 "
                        "{%0,%1,%2,%3}, {%4,%5,%6,%7}, {%8,%9}, {%0,%1,%2,%3};"
                        : "+f"(acc[mi][ni][0]), "+f"(acc[mi][ni][1]),
                          "+f"(acc[mi][ni][2]), "+f"(acc[mi][ni][3])
                        : "r"(a[mi][0]), "r"(a[mi][1]), "r"(a[mi][2]), "r"(a[mi][3]),
                          "r"(b0), "r"(b1));
                }
            }
        }
    }

    size_t ob = (size_t)n * CoN * HW + (size_t)y * Ww + x0;
#pragma unroll
    for (int ni = 0; ni < 8; ni++) {
        int o = 8 * ni + 2 * tc;
#pragma unroll
        for (int mi = 0; mi < 2; mi++) {
            int pr = warp * 32 + mi * 16 + gr;
            out[ob + (size_t)o * HW + pr]           = acc[mi][ni][0];
            out[ob + (size_t)(o + 1) * HW + pr]     = acc[mi][ni][1];
            out[ob + (size_t)o * HW + pr + 8]       = acc[mi][ni][2];
            out[ob + (size_t)(o + 1) * HW + pr + 8] = acc[mi][ni][3];
        }
    }
}

// ---------------------------------------------------------------------------
extern "C" void kernel_launch(void* const* d_in, const int* in_sizes, int n_in,
                              void* d_out, int out_size)
{
    const float* x    = (const float*)d_in[0];
    const float* woff = (const float*)d_in[1];
    const float* boff = (const float*)d_in[2];
    const float* wdef = (const float*)d_in[3];
    const float* bdef = (const float*)d_in[4];
    float* out = (float*)d_out;

    wfrag_kernel<<<(9 * 8 * 8 * 32 + 255) / 256, 256>>>(wdef);
    wofrag_kernel<<<(72 * 3 * 32 + 255) / 256, 256>>>(woff);
    offset_mma_kernel<<<dim3(Ww / 128, Hh, Nn), 128>>>(x, boff);
    deform_mma_kernel<<<dim3(Ww / 128, Hh, Nn), 128>>>(x, bdef, out);
}

// round 7
// speedup vs baseline: 1.3572x; 1.0558x over previous
#include <cuda_runtime.h>
#include <cuda_bf16.h>

#define Nn  8
#define Cc  64
#define Hh  128
#define Ww  512
#define CoN 64
#define HW  (Hh * Ww)      // 65536
#define NOFF 18
#define SSTR 36            // deform tile stride (floats) for 32-ch chunk
#define XSTR 136           // offset-conv x-tile stride

// Scratch: offsets and tf32 B-fragment tables.
__device__ float  g_off[(size_t)Nn * NOFF * HW];   // ~36 MB
__device__ float2 g_wfrag[9 * 8 * 8 * 32];         // deform B frags [t][k][ni][lane]
__device__ float2 g_wofrag[72 * 3 * 32];           // offset B frags

__device__ __forceinline__ unsigned f2tf32(float v) {
    unsigned u;
    asm("cvt.rna.tf32.f32 %0, %1;" : "=r"(u) : "f"(v));
    return u;
}

// ---------------------------------------------------------------------------
// Kernel 0a: deform B fragments (m16n8k8 tf32).
// ---------------------------------------------------------------------------
__global__ void wfrag_kernel(const float* __restrict__ wdef) {
    int idx = blockIdx.x * 256 + threadIdx.x;
    if (idx >= 9 * 8 * 8 * 32) return;
    int lane = idx & 31;
    int ni   = (idx >> 5) & 7;
    int k    = (idx >> 8) & 7;
    int t    = idx >> 11;
    int c = 8 * k + (lane & 3);
    int o = 8 * ni + (lane >> 2);
    float b0 = wdef[(o * 64 + c) * 9 + t];
    float b1 = wdef[(o * 64 + c + 4) * 9 + t];
    g_wfrag[idx] = make_float2(__uint_as_float(f2tf32(b0)),
                               __uint_as_float(f2tf32(b1)));
}

// ---------------------------------------------------------------------------
// Kernel 0b: offset-conv B fragments (oc padded 18 -> 24).
// ---------------------------------------------------------------------------
__global__ void wofrag_kernel(const float* __restrict__ woff) {
    int idx = blockIdx.x * 256 + threadIdx.x;
    if (idx >= 72 * 3 * 32) return;
    int lane = idx & 31;
    int rem  = idx >> 5;
    int ni   = rem % 3;
    int ks   = rem / 3;
    int gr = lane >> 2, tc = lane & 3;
    int k0 = 8 * ks + tc;
    int oc = 8 * ni + gr;
    float b0 = (oc < 18) ? woff[oc * 576 + k0]     : 0.0f;
    float b1 = (oc < 18) ? woff[oc * 576 + k0 + 4] : 0.0f;
    g_wofrag[(ks * 3 + ni) * 32 + lane] =
        make_float2(__uint_as_float(f2tf32(b0)), __uint_as_float(f2tf32(b1)));
}

// ---------------------------------------------------------------------------
// Kernel 1: offset conv via tf32 MMA — Round-4 version verbatim (261 us).
// ---------------------------------------------------------------------------
__global__ void __launch_bounds__(128) offset_mma_kernel(
    const float* __restrict__ xin,
    const float* __restrict__ boff)
{
    __shared__ float sx[24 * XSTR];

    int tid  = threadIdx.x;
    int lane = tid & 31;
    int warp = tid >> 5;
    int gr   = lane >> 2;
    int tc   = lane & 3;

    int x0 = blockIdx.x * 128;
    int y  = blockIdx.y;
    int n  = blockIdx.z;

    float acc[2][3][4];
#pragma unroll
    for (int ni = 0; ni < 3; ni++) {
        int oc = 8 * ni + 2 * tc;
        float blo = (oc < 18)     ? __ldg(&boff[oc])     : 0.0f;
        float bhi = (oc + 1 < 18) ? __ldg(&boff[oc + 1]) : 0.0f;
#pragma unroll
        for (int mi = 0; mi < 2; mi++) {
            acc[mi][ni][0] = blo; acc[mi][ni][1] = bhi;
            acc[mi][ni][2] = blo; acc[mi][ni][3] = bhi;
        }
    }

    const float* xb = xin + (size_t)n * Cc * HW;

    for (int ch = 0; ch < 8; ch++) {
        __syncthreads();
        for (int idx = tid; idx < 3120; idx += 128) {
            int c   = idx / 390;
            int r   = idx - 390 * c;
            int i   = r / 130;
            int col = r - 130 * i;
            int yy = y + i - 1;
            int xx = x0 + col - 1;
            float v = 0.0f;
            if (yy >= 0 && yy < Hh && xx >= 0 && xx < Ww)
                v = xb[(size_t)(ch * 8 + c) * HW + yy * Ww + xx];
            sx[(c * 3 + i) * XSTR + col] = __uint_as_float(f2tf32(v));
        }
        __syncthreads();

#pragma unroll
        for (int kk = 0; kk < 9; kk++) {
            int kl = 8 * kk + tc;
            int c0 = kl / 9,  t0 = kl - 9 * c0;
            int i0 = t0 / 3,  j0 = t0 - 3 * i0;
            int kl2 = kl + 4;
            int c1 = kl2 / 9, t1 = kl2 - 9 * c1;
            int i1 = t1 / 3,  j1 = t1 - 3 * i1;
            int off0 = (c0 * 3 + i0) * XSTR + j0;
            int off1 = (c1 * 3 + i1) * XSTR + j1;

            const float2* wf = g_wofrag + (size_t)(ch * 9 + kk) * 96;
            float2 bfr[3];
#pragma unroll
            for (int ni = 0; ni < 3; ni++) bfr[ni] = __ldg(&wf[ni * 32 + lane]);

#pragma unroll
            for (int mi = 0; mi < 2; mi++) {
                int m = warp * 32 + mi * 16 + gr;
                unsigned a0 = __float_as_uint(sx[off0 + m]);
                unsigned a1 = __float_as_uint(sx[off0 + m + 8]);
                unsigned a2 = __float_as_uint(sx[off1 + m]);
                unsigned a3 = __float_as_uint(sx[off1 + m + 8]);
#pragma unroll
                for (int ni = 0; ni < 3; ni++) {
                    unsigned b0 = __float_as_uint(bfr[ni].x);
                    unsigned b1 = __float_as_uint(bfr[ni].y);
                    asm volatile(
                        "mma.sync.aligned.m16n8k8.row.col.f32.tf32.tf32.f32 "
                        "{%0,%1,%2,%3}, {%4,%5,%6,%7}, {%8,%9}, {%0,%1,%2,%3};"
                        : "+f"(acc[mi][ni][0]), "+f"(acc[mi][ni][1]),
                          "+f"(acc[mi][ni][2]), "+f"(acc[mi][ni][3])
                        : "r"(a0), "r"(a1), "r"(a2), "r"(a3),
                          "r"(b0), "r"(b1));
                }
            }
        }
    }

    size_t ob = (size_t)n * NOFF * HW + (size_t)y * Ww + x0;
#pragma unroll
    for (int ni = 0; ni < 3; ni++) {
        int oc = 8 * ni + 2 * tc;
#pragma unroll
        for (int mi = 0; mi < 2; mi++) {
            int pr = warp * 32 + mi * 16 + gr;
            if (oc < 18) {
                g_off[ob + (size_t)oc * HW + pr]     = acc[mi][ni][0];
                g_off[ob + (size_t)oc * HW + pr + 8] = acc[mi][ni][2];
            }
            if (oc + 1 < 18) {
                g_off[ob + (size_t)(oc + 1) * HW + pr]     = acc[mi][ni][1];
                g_off[ob + (size_t)(oc + 1) * HW + pr + 8] = acc[mi][ni][3];
            }
        }
    }
}

// ---------------------------------------------------------------------------
// Kernel 2: deformable conv via tf32 MMA, NCHW gather, warp-private sync,
// K CHUNKED 2x32: smem tile halved to 18.4 KB -> ~12 CTAs/SM (occupancy 2x).
// Gather batches 4 channels into float4 -> 8 STS.128 per chunk.
// ---------------------------------------------------------------------------
__global__ void __launch_bounds__(128) deform_mma_kernel(
    const float* __restrict__ xin,
    const float* __restrict__ bdef,
    float* __restrict__ out)
{
    __shared__ __align__(16) float sS[128 * SSTR];   // 18.4 KB, warp-private quarters

    int tid  = threadIdx.x;
    int lane = tid & 31;
    int warp = tid >> 5;
    int gr   = lane >> 2;
    int tc   = lane & 3;

    int x0 = blockIdx.x * 128;
    int y  = blockIdx.y;
    int n  = blockIdx.z;
    int xg = x0 + tid;

    float acc[2][8][4];
#pragma unroll
    for (int ni = 0; ni < 8; ni++) {
        float blo = __ldg(&bdef[8 * ni + 2 * tc]);
        float bhi = __ldg(&bdef[8 * ni + 2 * tc + 1]);
#pragma unroll
        for (int mi = 0; mi < 2; mi++) {
            acc[mi][ni][0] = blo; acc[mi][ni][1] = bhi;
            acc[mi][ni][2] = blo; acc[mi][ni][3] = bhi;
        }
    }

    const float* xb   = xin + (size_t)n * Cc * HW;
    const float* offb = g_off + (size_t)n * NOFF * HW + (size_t)y * Ww + xg;

    for (int t = 0; t < 9; t++) {
        float dy = offb[(size_t)(2 * t) * HW];
        float dx = offb[(size_t)(2 * t + 1) * HW];
        int i = t / 3, j = t % 3;
        float py = (float)(y + i - 1) + dy;
        float px = (float)(xg + j - 1) + dx;

        float fy = floorf(py), fx = floorf(px);
        float wy1 = py - fy, wx1 = px - fx;
        float wy0 = 1.0f - wy1, wx0 = 1.0f - wx1;
        int iy0 = (int)fy, ix0 = (int)fx;
        int iy1 = iy0 + 1, ix1 = ix0 + 1;

        float gy0 = (iy0 >= 0 && iy0 < Hh) ? wy0 : 0.0f;
        float gy1 = (iy1 >= 0 && iy1 < Hh) ? wy1 : 0.0f;
        float gx0 = (ix0 >= 0 && ix0 < Ww) ? wx0 : 0.0f;
        float gx1 = (ix1 >= 0 && ix1 < Ww) ? wx1 : 0.0f;
        float c00 = gy0 * gx0, c01 = gy0 * gx1;
        float c10 = gy1 * gx0, c11 = gy1 * gx1;

        int yc0 = min(max(iy0, 0), Hh - 1), yc1 = min(max(iy1, 0), Hh - 1);
        int xc0 = min(max(ix0, 0), Ww - 1), xc1 = min(max(ix1, 0), Ww - 1);
        int o00 = yc0 * Ww + xc0, o01 = yc0 * Ww + xc1;
        int o10 = yc1 * Ww + xc0, o11 = yc1 * Ww + xc1;

#pragma unroll
        for (int h = 0; h < 2; h++) {
            __syncwarp();   // this warp's previous MMA reads are done
            {
                float4* srow = (float4*)(sS + tid * SSTR);
                const float* p = xb + (size_t)(h * 32) * HW;
#pragma unroll
                for (int q = 0; q < 8; q++) {
                    float4 v;
                    {
                        float a = c00 * p[o00];
                        a = fmaf(c01, p[o01], a);
                        a = fmaf(c10, p[o10], a);
                        a = fmaf(c11, p[o11], a);
                        v.x = __uint_as_float(f2tf32(a));  p += HW;
                    }
                    {
                        float a = c00 * p[o00];
                        a = fmaf(c01, p[o01], a);
                        a = fmaf(c10, p[o10], a);
                        a = fmaf(c11, p[o11], a);
                        v.y = __uint_as_float(f2tf32(a));  p += HW;
                    }
                    {
                        float a = c00 * p[o00];
                        a = fmaf(c01, p[o01], a);
                        a = fmaf(c10, p[o10], a);
                        a = fmaf(c11, p[o11], a);
                        v.z = __uint_as_float(f2tf32(a));  p += HW;
                    }
                    {
                        float a = c00 * p[o00];
                        a = fmaf(c01, p[o01], a);
                        a = fmaf(c10, p[o10], a);
                        a = fmaf(c11, p[o11], a);
                        v.w = __uint_as_float(f2tf32(a));  p += HW;
                    }
                    srow[q] = v;
                }
            }
            __syncwarp();   // tile rows for this warp visible

            const float2* wf = g_wfrag + (size_t)t * 8 * 8 * 32;
#pragma unroll
            for (int kq = 0; kq < 4; kq++) {
                int k = 4 * h + kq;   // global k-step for B frags
                unsigned a[2][4];
#pragma unroll
                for (int mi = 0; mi < 2; mi++) {
                    const float* base = sS + (warp * 32 + mi * 16 + gr) * SSTR + 8 * kq + tc;
                    a[mi][0] = __float_as_uint(base[0]);
                    a[mi][1] = __float_as_uint(base[8 * SSTR]);
                    a[mi][2] = __float_as_uint(base[4]);
                    a[mi][3] = __float_as_uint(base[8 * SSTR + 4]);
                }
#pragma unroll
                for (int ni = 0; ni < 8; ni++) {
                    float2 b = __ldg(&wf[(k * 8 + ni) * 32 + lane]);
                    unsigned b0 = __float_as_uint(b.x);
                    unsigned b1 = __float_as_uint(b.y);
#pragma unroll
                    for (int mi = 0; mi < 2; mi++) {
                        asm volatile(
                            "mma.sync.aligned.m16n8k8.row.col.f32.tf32.tf32.f32 "
                            "{%0,%1,%2,%3}, {%4,%5,%6,%7}, {%8,%9}, {%0,%1,%2,%3};"
                            : "+f"(acc[mi][ni][0]), "+f"(acc[mi][ni][1]),
                              "+f"(acc[mi][ni][2]), "+f"(acc[mi][ni][3])
                            : "r"(a[mi][0]), "r"(a[mi][1]), "r"(a[mi][2]), "r"(a[mi][3]),
                              "r"(b0), "r"(b1));
                    }
                }
            }
        }
    }

    size_t ob = (size_t)n * CoN * HW + (size_t)y * Ww + x0;
#pragma unroll
    for (int ni = 0; ni < 8; ni++) {
        int o = 8 * ni + 2 * tc;
#pragma unroll
        for (int mi = 0; mi < 2; mi++) {
            int pr = warp * 32 + mi * 16 + gr;
            out[ob + (size_t)o * HW + pr]           = acc[mi][ni][0];
            out[ob + (size_t)(o + 1) * HW + pr]     = acc[mi][ni][1];
            out[ob + (size_t)o * HW + pr + 8]       = acc[mi][ni][2];
            out[ob + (size_t)(o + 1) * HW + pr + 8] = acc[mi][ni][3];
        }
    }
}

// ---------------------------------------------------------------------------
extern "C" void kernel_launch(void* const* d_in, const int* in_sizes, int n_in,
                              void* d_out, int out_size)
{
    const float* x    = (const float*)d_in[0];
    const float* woff = (const float*)d_in[1];
    const float* boff = (const float*)d_in[2];
    const float* wdef = (const float*)d_in[3];
    const float* bdef = (const float*)d_in[4];
    float* out = (float*)d_out;

    wfrag_kernel<<<(9 * 8 * 8 * 32 + 255) / 256, 256>>>(wdef);
    wofrag_kernel<<<(72 * 3 * 32 + 255) / 256, 256>>>(woff);
    offset_mma_kernel<<<dim3(Ww / 128, Hh, Nn), 128>>>(x, boff);
    deform_mma_kernel<<<dim3(Ww / 128, Hh, Nn), 128>>>(x, bdef, out);
}

// round 8
// speedup vs baseline: 1.5662x; 1.1541x over previous
#include <cuda_runtime.h>
#include <cuda_bf16.h>

#define Nn  8
#define Cc  64
#define Hh  128
#define Ww  512
#define CoN 64
#define HW  (Hh * Ww)      // 65536
#define NOFF 18
#define SSTR 68            // deform tile stride: 272B, 16B-aligned, conflict-free
#define XSTR 136           // offset-conv x-tile stride

// Scratch: offsets and tf32 B-fragment tables.
__device__ float  g_off[(size_t)Nn * NOFF * HW];   // ~36 MB
__device__ float2 g_wfrag[9 * 8 * 8 * 32];         // deform B frags [t][k][ni][lane]
__device__ float2 g_wofrag[72 * 3 * 32];           // offset B frags

__device__ __forceinline__ unsigned f2tf32(float v) {
    unsigned u;
    asm("cvt.rna.tf32.f32 %0, %1;" : "=r"(u) : "f"(v));
    return u;
}

// ---------------------------------------------------------------------------
// Kernel 0a: deform B fragments (m16n8k8 tf32).
// ---------------------------------------------------------------------------
__global__ void wfrag_kernel(const float* __restrict__ wdef) {
    int idx = blockIdx.x * 256 + threadIdx.x;
    if (idx >= 9 * 8 * 8 * 32) return;
    int lane = idx & 31;
    int ni   = (idx >> 5) & 7;
    int k    = (idx >> 8) & 7;
    int t    = idx >> 11;
    int c = 8 * k + (lane & 3);
    int o = 8 * ni + (lane >> 2);
    float b0 = wdef[(o * 64 + c) * 9 + t];
    float b1 = wdef[(o * 64 + c + 4) * 9 + t];
    g_wfrag[idx] = make_float2(__uint_as_float(f2tf32(b0)),
                               __uint_as_float(f2tf32(b1)));
}

// ---------------------------------------------------------------------------
// Kernel 0b: offset-conv B fragments (oc padded 18 -> 24).
// ---------------------------------------------------------------------------
__global__ void wofrag_kernel(const float* __restrict__ woff) {
    int idx = blockIdx.x * 256 + threadIdx.x;
    if (idx >= 72 * 3 * 32) return;
    int lane = idx & 31;
    int rem  = idx >> 5;
    int ni   = rem % 3;
    int ks   = rem / 3;
    int gr = lane >> 2, tc = lane & 3;
    int k0 = 8 * ks + tc;
    int oc = 8 * ni + gr;
    float b0 = (oc < 18) ? woff[oc * 576 + k0]     : 0.0f;
    float b1 = (oc < 18) ? woff[oc * 576 + k0 + 4] : 0.0f;
    g_wofrag[(ks * 3 + ni) * 32 + lane] =
        make_float2(__uint_as_float(f2tf32(b0)), __uint_as_float(f2tf32(b1)));
}

// ---------------------------------------------------------------------------
// Kernel 1: offset conv via tf32 MMA — Round-4 version verbatim.
// ---------------------------------------------------------------------------
__global__ void __launch_bounds__(128) offset_mma_kernel(
    const float* __restrict__ xin,
    const float* __restrict__ boff)
{
    __shared__ float sx[24 * XSTR];

    int tid  = threadIdx.x;
    int lane = tid & 31;
    int warp = tid >> 5;
    int gr   = lane >> 2;
    int tc   = lane & 3;

    int x0 = blockIdx.x * 128;
    int y  = blockIdx.y;
    int n  = blockIdx.z;

    float acc[2][3][4];
#pragma unroll
    for (int ni = 0; ni < 3; ni++) {
        int oc = 8 * ni + 2 * tc;
        float blo = (oc < 18)     ? __ldg(&boff[oc])     : 0.0f;
        float bhi = (oc + 1 < 18) ? __ldg(&boff[oc + 1]) : 0.0f;
#pragma unroll
        for (int mi = 0; mi < 2; mi++) {
            acc[mi][ni][0] = blo; acc[mi][ni][1] = bhi;
            acc[mi][ni][2] = blo; acc[mi][ni][3] = bhi;
        }
    }

    const float* xb = xin + (size_t)n * Cc * HW;

    for (int ch = 0; ch < 8; ch++) {
        __syncthreads();
        for (int idx = tid; idx < 3120; idx += 128) {
            int c   = idx / 390;
            int r   = idx - 390 * c;
            int i   = r / 130;
            int col = r - 130 * i;
            int yy = y + i - 1;
            int xx = x0 + col - 1;
            float v = 0.0f;
            if (yy >= 0 && yy < Hh && xx >= 0 && xx < Ww)
                v = xb[(size_t)(ch * 8 + c) * HW + yy * Ww + xx];
            sx[(c * 3 + i) * XSTR + col] = __uint_as_float(f2tf32(v));
        }
        __syncthreads();

#pragma unroll
        for (int kk = 0; kk < 9; kk++) {
            int kl = 8 * kk + tc;
            int c0 = kl / 9,  t0 = kl - 9 * c0;
            int i0 = t0 / 3,  j0 = t0 - 3 * i0;
            int kl2 = kl + 4;
            int c1 = kl2 / 9, t1 = kl2 - 9 * c1;
            int i1 = t1 / 3,  j1 = t1 - 3 * i1;
            int off0 = (c0 * 3 + i0) * XSTR + j0;
            int off1 = (c1 * 3 + i1) * XSTR + j1;

            const float2* wf = g_wofrag + (size_t)(ch * 9 + kk) * 96;
            float2 bfr[3];
#pragma unroll
            for (int ni = 0; ni < 3; ni++) bfr[ni] = __ldg(&wf[ni * 32 + lane]);

#pragma unroll
            for (int mi = 0; mi < 2; mi++) {
                int m = warp * 32 + mi * 16 + gr;
                unsigned a0 = __float_as_uint(sx[off0 + m]);
                unsigned a1 = __float_as_uint(sx[off0 + m + 8]);
                unsigned a2 = __float_as_uint(sx[off1 + m]);
                unsigned a3 = __float_as_uint(sx[off1 + m + 8]);
#pragma unroll
                for (int ni = 0; ni < 3; ni++) {
                    unsigned b0 = __float_as_uint(bfr[ni].x);
                    unsigned b1 = __float_as_uint(bfr[ni].y);
                    asm volatile(
                        "mma.sync.aligned.m16n8k8.row.col.f32.tf32.tf32.f32 "
                        "{%0,%1,%2,%3}, {%4,%5,%6,%7}, {%8,%9}, {%0,%1,%2,%3};"
                        : "+f"(acc[mi][ni][0]), "+f"(acc[mi][ni][1]),
                          "+f"(acc[mi][ni][2]), "+f"(acc[mi][ni][3])
                        : "r"(a0), "r"(a1), "r"(a2), "r"(a3),
                          "r"(b0), "r"(b1));
                }
            }
        }
    }

    size_t ob = (size_t)n * NOFF * HW + (size_t)y * Ww + x0;
#pragma unroll
    for (int ni = 0; ni < 3; ni++) {
        int oc = 8 * ni + 2 * tc;
#pragma unroll
        for (int mi = 0; mi < 2; mi++) {
            int pr = warp * 32 + mi * 16 + gr;
            if (oc < 18) {
                g_off[ob + (size_t)oc * HW + pr]     = acc[mi][ni][0];
                g_off[ob + (size_t)oc * HW + pr + 8] = acc[mi][ni][2];
            }
            if (oc + 1 < 18) {
                g_off[ob + (size_t)(oc + 1) * HW + pr]     = acc[mi][ni][1];
                g_off[ob + (size_t)(oc + 1) * HW + pr + 8] = acc[mi][ni][3];
            }
        }
    }
}

// ---------------------------------------------------------------------------
// Kernel 2: deformable conv, tf32 MMA, och SPLIT across warps.
// CTA = 128 threads = 64 pixels x 2 och-halves. Warp w: pixel group g=w&1
// (32 px), och half h=w>>1 (32 ch). Warp w gathers channels [32h,32h+32) of
// pixel (tid&63) -> exactly the tile quadrant the pair {g, g+2} consumes.
// Sync = named barrier per pixel-group pair (64 threads), so the two pairs
// pipeline independently. acc = 32 regs/thread; launch_bounds(128,6).
// ---------------------------------------------------------------------------
__global__ void __launch_bounds__(128, 6) deform_mma_kernel(
    const float* __restrict__ xin,
    const float* __restrict__ bdef,
    float* __restrict__ out)
{
    __shared__ __align__(16) float sS[64 * SSTR];   // 17408 B

    int tid  = threadIdx.x;
    int lane = tid & 31;
    int warp = tid >> 5;
    int g    = warp & 1;      // pixel group
    int h    = warp >> 1;     // channel half (gather ch + MMA och)
    int gr   = lane >> 2;
    int tc   = lane & 3;

    int x0  = blockIdx.x * 64;
    int y   = blockIdx.y;
    int n   = blockIdx.z;
    int pxl = tid & 63;       // gather pixel within CTA
    int xg  = x0 + pxl;

    float acc[2][4][4];
#pragma unroll
    for (int ni = 0; ni < 4; ni++) {
        int ni_g = 4 * h + ni;
        float blo = __ldg(&bdef[8 * ni_g + 2 * tc]);
        float bhi = __ldg(&bdef[8 * ni_g + 2 * tc + 1]);
#pragma unroll
        for (int mi = 0; mi < 2; mi++) {
            acc[mi][ni][0] = blo; acc[mi][ni][1] = bhi;
            acc[mi][ni][2] = blo; acc[mi][ni][3] = bhi;
        }
    }

    const float* xb   = xin + (size_t)n * Cc * HW + (size_t)(h * 32) * HW;
    const float* offb = g_off + (size_t)n * NOFF * HW + (size_t)y * Ww + xg;

    // prefetch tap-0 offsets
    float dy = offb[0];
    float dx = offb[(size_t)HW];

    for (int t = 0; t < 9; t++) {
        int i = t / 3, j = t % 3;
        float py  = (float)(y + i - 1) + dy;
        float pxf = (float)(xg + j - 1) + dx;

        // prefetch next tap's offsets (overlaps with gather + MMA below)
        if (t < 8) {
            dy = offb[(size_t)(2 * t + 2) * HW];
            dx = offb[(size_t)(2 * t + 3) * HW];
        }

        float fy = floorf(py), fx = floorf(pxf);
        float wy1 = py - fy, wx1 = pxf - fx;
        float wy0 = 1.0f - wy1, wx0 = 1.0f - wx1;
        int iy0 = (int)fy, ix0 = (int)fx;
        int iy1 = iy0 + 1, ix1 = ix0 + 1;

        float gy0 = (iy0 >= 0 && iy0 < Hh) ? wy0 : 0.0f;
        float gy1 = (iy1 >= 0 && iy1 < Hh) ? wy1 : 0.0f;
        float gx0 = (ix0 >= 0 && ix0 < Ww) ? wx0 : 0.0f;
        float gx1 = (ix1 >= 0 && ix1 < Ww) ? wx1 : 0.0f;
        float c00 = gy0 * gx0, c01 = gy0 * gx1;
        float c10 = gy1 * gx0, c11 = gy1 * gx1;

        int yc0 = min(max(iy0, 0), Hh - 1), yc1 = min(max(iy1, 0), Hh - 1);
        int xc0 = min(max(ix0, 0), Ww - 1), xc1 = min(max(ix1, 0), Ww - 1);
        int o00 = yc0 * Ww + xc0, o01 = yc0 * Ww + xc1;
        int o10 = yc1 * Ww + xc0, o11 = yc1 * Ww + xc1;

        // pair barrier: previous tap's MMA reads of our rows are done
        asm volatile("bar.sync %0, %1;" :: "r"(1 + g), "r"(64) : "memory");

        {   // gather 32 channels of pixel pxl into tile quadrant
            float4* srow = (float4*)(sS + pxl * SSTR + 32 * h);
            const float* p = xb;
#pragma unroll
            for (int q = 0; q < 8; q++) {
                float4 v;
                {
                    float a = c00 * p[o00];
                    a = fmaf(c01, p[o01], a);
                    a = fmaf(c10, p[o10], a);
                    a = fmaf(c11, p[o11], a);
                    v.x = __uint_as_float(f2tf32(a));  p += HW;
                }
                {
                    float a = c00 * p[o00];
                    a = fmaf(c01, p[o01], a);
                    a = fmaf(c10, p[o10], a);
                    a = fmaf(c11, p[o11], a);
                    v.y = __uint_as_float(f2tf32(a));  p += HW;
                }
                {
                    float a = c00 * p[o00];
                    a = fmaf(c01, p[o01], a);
                    a = fmaf(c10, p[o10], a);
                    a = fmaf(c11, p[o11], a);
                    v.z = __uint_as_float(f2tf32(a));  p += HW;
                }
                {
                    float a = c00 * p[o00];
                    a = fmaf(c01, p[o01], a);
                    a = fmaf(c10, p[o10], a);
                    a = fmaf(c11, p[o11], a);
                    v.w = __uint_as_float(f2tf32(a));  p += HW;
                }
                srow[q] = v;
            }
        }

        // pair barrier: both halves of our pixel-group rows are written
        asm volatile("bar.sync %0, %1;" :: "r"(1 + g), "r"(64) : "memory");

        const float2* wf = g_wfrag + (size_t)t * 8 * 8 * 32;
#pragma unroll
        for (int k = 0; k < 8; k++) {
            unsigned a[2][4];
#pragma unroll
            for (int mi = 0; mi < 2; mi++) {
                const float* base = sS + (32 * g + mi * 16 + gr) * SSTR + 8 * k + tc;
                a[mi][0] = __float_as_uint(base[0]);
                a[mi][1] = __float_as_uint(base[8 * SSTR]);
                a[mi][2] = __float_as_uint(base[4]);
                a[mi][3] = __float_as_uint(base[8 * SSTR + 4]);
            }
#pragma unroll
            for (int ni = 0; ni < 4; ni++) {
                int ni_g = 4 * h + ni;
                float2 b = __ldg(&wf[(k * 8 + ni_g) * 32 + lane]);
                unsigned b0 = __float_as_uint(b.x);
                unsigned b1 = __float_as_uint(b.y);
#pragma unroll
                for (int mi = 0; mi < 2; mi++) {
                    asm volatile(
                        "mma.sync.aligned.m16n8k8.row.col.f32.tf32.tf32.f32 "
                        "{%0,%1,%2,%3}, {%4,%5,%6,%7}, {%8,%9}, {%0,%1,%2,%3};"
                        : "+f"(acc[mi][ni][0]), "+f"(acc[mi][ni][1]),
                          "+f"(acc[mi][ni][2]), "+f"(acc[mi][ni][3])
                        : "r"(a[mi][0]), "r"(a[mi][1]), "r"(a[mi][2]), "r"(a[mi][3]),
                          "r"(b0), "r"(b1));
                }
            }
        }
    }

    // epilogue: warp writes its 32 px x 32 och
    size_t ob = (size_t)n * CoN * HW + (size_t)y * Ww + x0;
#pragma unroll
    for (int ni = 0; ni < 4; ni++) {
        int o = 8 * (4 * h + ni) + 2 * tc;
#pragma unroll
        for (int mi = 0; mi < 2; mi++) {
            int pr = 32 * g + mi * 16 + gr;
            out[ob + (size_t)o * HW + pr]           = acc[mi][ni][0];
            out[ob + (size_t)(o + 1) * HW + pr]     = acc[mi][ni][1];
            out[ob + (size_t)o * HW + pr + 8]       = acc[mi][ni][2];
            out[ob + (size_t)(o + 1) * HW + pr + 8] = acc[mi][ni][3];
        }
    }
}

// ---------------------------------------------------------------------------
extern "C" void kernel_launch(void* const* d_in, const int* in_sizes, int n_in,
                              void* d_out, int out_size)
{
    const float* x    = (const float*)d_in[0];
    const float* woff = (const float*)d_in[1];
    const float* boff = (const float*)d_in[2];
    const float* wdef = (const float*)d_in[3];
    const float* bdef = (const float*)d_in[4];
    float* out = (float*)d_out;

    wfrag_kernel<<<(9 * 8 * 8 * 32 + 255) / 256, 256>>>(wdef);
    wofrag_kernel<<<(72 * 3 * 32 + 255) / 256, 256>>>(woff);
    offset_mma_kernel<<<dim3(Ww / 128, Hh, Nn), 128>>>(x, boff);
    deform_mma_kernel<<<dim3(Ww / 64, Hh, Nn), 128>>>(x, bdef, out);
}

// round 9
// speedup vs baseline: 1.6753x; 1.0696x over previous
#include <cuda_runtime.h>
#include <cuda_bf16.h>

#define Nn  8
#define Cc  64
#define Hh  128
#define Ww  512
#define CoN 64
#define HW  (Hh * Ww)      // 65536
#define NOFF 18
#define SSTR 68            // deform tile stride: 272B, 16B-aligned, conflict-free
#define XSTR 136           // offset-conv x-tile stride

// Scratch: offsets and tf32 B-fragment tables.
__device__ float  g_off[(size_t)Nn * NOFF * HW];   // ~36 MB
__device__ float2 g_wfrag[9 * 8 * 8 * 32];         // deform B frags [t][k][ni][lane]
__device__ float2 g_wofrag[72 * 3 * 32];           // offset B frags

__device__ __forceinline__ unsigned f2tf32(float v) {
    unsigned u;
    asm("cvt.rna.tf32.f32 %0, %1;" : "=r"(u) : "f"(v));
    return u;
}

// ---------------------------------------------------------------------------
// Kernel 0a: deform B fragments (m16n8k8 tf32).
// ---------------------------------------------------------------------------
__global__ void wfrag_kernel(const float* __restrict__ wdef) {
    int idx = blockIdx.x * 256 + threadIdx.x;
    if (idx >= 9 * 8 * 8 * 32) return;
    int lane = idx & 31;
    int ni   = (idx >> 5) & 7;
    int k    = (idx >> 8) & 7;
    int t    = idx >> 11;
    int c = 8 * k + (lane & 3);
    int o = 8 * ni + (lane >> 2);
    float b0 = wdef[(o * 64 + c) * 9 + t];
    float b1 = wdef[(o * 64 + c + 4) * 9 + t];
    g_wfrag[idx] = make_float2(__uint_as_float(f2tf32(b0)),
                               __uint_as_float(f2tf32(b1)));
}

// ---------------------------------------------------------------------------
// Kernel 0b: offset-conv B fragments (oc padded 18 -> 24).
// ---------------------------------------------------------------------------
__global__ void wofrag_kernel(const float* __restrict__ woff) {
    int idx = blockIdx.x * 256 + threadIdx.x;
    if (idx >= 72 * 3 * 32) return;
    int lane = idx & 31;
    int rem  = idx >> 5;
    int ni   = rem % 3;
    int ks   = rem / 3;
    int gr = lane >> 2, tc = lane & 3;
    int k0 = 8 * ks + tc;
    int oc = 8 * ni + gr;
    float b0 = (oc < 18) ? woff[oc * 576 + k0]     : 0.0f;
    float b1 = (oc < 18) ? woff[oc * 576 + k0 + 4] : 0.0f;
    g_wofrag[(ks * 3 + ni) * 32 + lane] =
        make_float2(__uint_as_float(f2tf32(b0)), __uint_as_float(f2tf32(b1)));
}

// ---------------------------------------------------------------------------
// Kernel 1: offset conv via tf32 MMA — Round-4 version verbatim.
// ---------------------------------------------------------------------------
__global__ void __launch_bounds__(128) offset_mma_kernel(
    const float* __restrict__ xin,
    const float* __restrict__ boff)
{
    __shared__ float sx[24 * XSTR];

    int tid  = threadIdx.x;
    int lane = tid & 31;
    int warp = tid >> 5;
    int gr   = lane >> 2;
    int tc   = lane & 3;

    int x0 = blockIdx.x * 128;
    int y  = blockIdx.y;
    int n  = blockIdx.z;

    float acc[2][3][4];
#pragma unroll
    for (int ni = 0; ni < 3; ni++) {
        int oc = 8 * ni + 2 * tc;
        float blo = (oc < 18)     ? __ldg(&boff[oc])     : 0.0f;
        float bhi = (oc + 1 < 18) ? __ldg(&boff[oc + 1]) : 0.0f;
#pragma unroll
        for (int mi = 0; mi < 2; mi++) {
            acc[mi][ni][0] = blo; acc[mi][ni][1] = bhi;
            acc[mi][ni][2] = blo; acc[mi][ni][3] = bhi;
        }
    }

    const float* xb = xin + (size_t)n * Cc * HW;

    for (int ch = 0; ch < 8; ch++) {
        __syncthreads();
        for (int idx = tid; idx < 3120; idx += 128) {
            int c   = idx / 390;
            int r   = idx - 390 * c;
            int i   = r / 130;
            int col = r - 130 * i;
            int yy = y + i - 1;
            int xx = x0 + col - 1;
            float v = 0.0f;
            if (yy >= 0 && yy < Hh && xx >= 0 && xx < Ww)
                v = xb[(size_t)(ch * 8 + c) * HW + yy * Ww + xx];
            sx[(c * 3 + i) * XSTR + col] = __uint_as_float(f2tf32(v));
        }
        __syncthreads();

#pragma unroll
        for (int kk = 0; kk < 9; kk++) {
            int kl = 8 * kk + tc;
            int c0 = kl / 9,  t0 = kl - 9 * c0;
            int i0 = t0 / 3,  j0 = t0 - 3 * i0;
            int kl2 = kl + 4;
            int c1 = kl2 / 9, t1 = kl2 - 9 * c1;
            int i1 = t1 / 3,  j1 = t1 - 3 * i1;
            int off0 = (c0 * 3 + i0) * XSTR + j0;
            int off1 = (c1 * 3 + i1) * XSTR + j1;

            const float2* wf = g_wofrag + (size_t)(ch * 9 + kk) * 96;
            float2 bfr[3];
#pragma unroll
            for (int ni = 0; ni < 3; ni++) bfr[ni] = __ldg(&wf[ni * 32 + lane]);

#pragma unroll
            for (int mi = 0; mi < 2; mi++) {
                int m = warp * 32 + mi * 16 + gr;
                unsigned a0 = __float_as_uint(sx[off0 + m]);
                unsigned a1 = __float_as_uint(sx[off0 + m + 8]);
                unsigned a2 = __float_as_uint(sx[off1 + m]);
                unsigned a3 = __float_as_uint(sx[off1 + m + 8]);
#pragma unroll
                for (int ni = 0; ni < 3; ni++) {
                    unsigned b0 = __float_as_uint(bfr[ni].x);
                    unsigned b1 = __float_as_uint(bfr[ni].y);
                    asm volatile(
                        "mma.sync.aligned.m16n8k8.row.col.f32.tf32.tf32.f32 "
                        "{%0,%1,%2,%3}, {%4,%5,%6,%7}, {%8,%9}, {%0,%1,%2,%3};"
                        : "+f"(acc[mi][ni][0]), "+f"(acc[mi][ni][1]),
                          "+f"(acc[mi][ni][2]), "+f"(acc[mi][ni][3])
                        : "r"(a0), "r"(a1), "r"(a2), "r"(a3),
                          "r"(b0), "r"(b1));
                }
            }
        }
    }

    size_t ob = (size_t)n * NOFF * HW + (size_t)y * Ww + x0;
#pragma unroll
    for (int ni = 0; ni < 3; ni++) {
        int oc = 8 * ni + 2 * tc;
#pragma unroll
        for (int mi = 0; mi < 2; mi++) {
            int pr = warp * 32 + mi * 16 + gr;
            if (oc < 18) {
                g_off[ob + (size_t)oc * HW + pr]     = acc[mi][ni][0];
                g_off[ob + (size_t)oc * HW + pr + 8] = acc[mi][ni][2];
            }
            if (oc + 1 < 18) {
                g_off[ob + (size_t)(oc + 1) * HW + pr]     = acc[mi][ni][1];
                g_off[ob + (size_t)(oc + 1) * HW + pr + 8] = acc[mi][ni][3];
            }
        }
    }
}

// ---------------------------------------------------------------------------
// Kernel 2: deformable conv, tf32 MMA, och split across warps (Round 8)
// + DOUBLE-BUFFERED sample tile -> ONE barrier per tap.
// MMA(t) reads buf[t&1]; gather(t+1) writes buf[(t+1)&1] with no barrier
// after MMA. Buffer-reuse safety: at gather(t) start, partner has passed the
// tap-(t-1) barrier, which follows its gather(t-1), which follows its
// MMA(t-2) — the last reader of buf[t&1].
// ---------------------------------------------------------------------------
__global__ void __launch_bounds__(128, 6) deform_mma_kernel(
    const float* __restrict__ xin,
    const float* __restrict__ bdef,
    float* __restrict__ out)
{
    __shared__ __align__(16) float sS[2][64 * SSTR];   // 2 x 17408 B

    int tid  = threadIdx.x;
    int lane = tid & 31;
    int warp = tid >> 5;
    int g    = warp & 1;      // pixel group
    int h    = warp >> 1;     // channel half (gather ch + MMA och)
    int gr   = lane >> 2;
    int tc   = lane & 3;

    int x0  = blockIdx.x * 64;
    int y   = blockIdx.y;
    int n   = blockIdx.z;
    int pxl = tid & 63;       // gather pixel within CTA
    int xg  = x0 + pxl;

    float acc[2][4][4];
#pragma unroll
    for (int ni = 0; ni < 4; ni++) {
        int ni_g = 4 * h + ni;
        float blo = __ldg(&bdef[8 * ni_g + 2 * tc]);
        float bhi = __ldg(&bdef[8 * ni_g + 2 * tc + 1]);
#pragma unroll
        for (int mi = 0; mi < 2; mi++) {
            acc[mi][ni][0] = blo; acc[mi][ni][1] = bhi;
            acc[mi][ni][2] = blo; acc[mi][ni][3] = bhi;
        }
    }

    const float* xb   = xin + (size_t)n * Cc * HW + (size_t)(h * 32) * HW;
    const float* offb = g_off + (size_t)n * NOFF * HW + (size_t)y * Ww + xg;

    // prefetch tap-0 offsets
    float dy = offb[0];
    float dx = offb[(size_t)HW];

    for (int t = 0; t < 9; t++) {
        int i = t / 3, j = t % 3;
        float py  = (float)(y + i - 1) + dy;
        float pxf = (float)(xg + j - 1) + dx;

        // prefetch next tap's offsets (overlaps gather + MMA)
        if (t < 8) {
            dy = offb[(size_t)(2 * t + 2) * HW];
            dx = offb[(size_t)(2 * t + 3) * HW];
        }

        float fy = floorf(py), fx = floorf(pxf);
        float wy1 = py - fy, wx1 = pxf - fx;
        float wy0 = 1.0f - wy1, wx0 = 1.0f - wx1;
        int iy0 = (int)fy, ix0 = (int)fx;
        int iy1 = iy0 + 1, ix1 = ix0 + 1;

        float gy0 = (iy0 >= 0 && iy0 < Hh) ? wy0 : 0.0f;
        float gy1 = (iy1 >= 0 && iy1 < Hh) ? wy1 : 0.0f;
        float gx0 = (ix0 >= 0 && ix0 < Ww) ? wx0 : 0.0f;
        float gx1 = (ix1 >= 0 && ix1 < Ww) ? wx1 : 0.0f;
        float c00 = gy0 * gx0, c01 = gy0 * gx1;
        float c10 = gy1 * gx0, c11 = gy1 * gx1;

        int yc0 = min(max(iy0, 0), Hh - 1), yc1 = min(max(iy1, 0), Hh - 1);
        int xc0 = min(max(ix0, 0), Ww - 1), xc1 = min(max(ix1, 0), Ww - 1);
        int o00 = yc0 * Ww + xc0, o01 = yc0 * Ww + xc1;
        int o10 = yc1 * Ww + xc0, o11 = yc1 * Ww + xc1;

        float* buf = sS[t & 1];

        {   // gather 32 channels of pixel pxl into this buffer's quadrant
            float4* srow = (float4*)(buf + pxl * SSTR + 32 * h);
            const float* p = xb;
#pragma unroll
            for (int q = 0; q < 8; q++) {
                float4 v;
                {
                    float a = c00 * p[o00];
                    a = fmaf(c01, p[o01], a);
                    a = fmaf(c10, p[o10], a);
                    a = fmaf(c11, p[o11], a);
                    v.x = __uint_as_float(f2tf32(a));  p += HW;
                }
                {
                    float a = c00 * p[o00];
                    a = fmaf(c01, p[o01], a);
                    a = fmaf(c10, p[o10], a);
                    a = fmaf(c11, p[o11], a);
                    v.y = __uint_as_float(f2tf32(a));  p += HW;
                }
                {
                    float a = c00 * p[o00];
                    a = fmaf(c01, p[o01], a);
                    a = fmaf(c10, p[o10], a);
                    a = fmaf(c11, p[o11], a);
                    v.z = __uint_as_float(f2tf32(a));  p += HW;
                }
                {
                    float a = c00 * p[o00];
                    a = fmaf(c01, p[o01], a);
                    a = fmaf(c10, p[o10], a);
                    a = fmaf(c11, p[o11], a);
                    v.w = __uint_as_float(f2tf32(a));  p += HW;
                }
                srow[q] = v;
            }
        }

        // single pair barrier per tap: all quadrants of buf[t&1] written
        asm volatile("bar.sync %0, %1;" :: "r"(1 + g), "r"(64) : "memory");

        const float2* wf = g_wfrag + (size_t)t * 8 * 8 * 32;
#pragma unroll
        for (int k = 0; k < 8; k++) {
            unsigned a[2][4];
#pragma unroll
            for (int mi = 0; mi < 2; mi++) {
                const float* base = buf + (32 * g + mi * 16 + gr) * SSTR + 8 * k + tc;
                a[mi][0] = __float_as_uint(base[0]);
                a[mi][1] = __float_as_uint(base[8 * SSTR]);
                a[mi][2] = __float_as_uint(base[4]);
                a[mi][3] = __float_as_uint(base[8 * SSTR + 4]);
            }
#pragma unroll
            for (int ni = 0; ni < 4; ni++) {
                int ni_g = 4 * h + ni;
                float2 b = __ldg(&wf[(k * 8 + ni_g) * 32 + lane]);
                unsigned b0 = __float_as_uint(b.x);
                unsigned b1 = __float_as_uint(b.y);
#pragma unroll
                for (int mi = 0; mi < 2; mi++) {
                    asm volatile(
                        "mma.sync.aligned.m16n8k8.row.col.f32.tf32.tf32.f32 "
                        "{%0,%1,%2,%3}, {%4,%5,%6,%7}, {%8,%9}, {%0,%1,%2,%3};"
                        : "+f"(acc[mi][ni][0]), "+f"(acc[mi][ni][1]),
                          "+f"(acc[mi][ni][2]), "+f"(acc[mi][ni][3])
                        : "r"(a[mi][0]), "r"(a[mi][1]), "r"(a[mi][2]), "r"(a[mi][3]),
                          "r"(b0), "r"(b1));
                }
            }
        }
    }

    // epilogue: warp writes its 32 px x 32 och
    size_t ob = (size_t)n * CoN * HW + (size_t)y * Ww + x0;
#pragma unroll
    for (int ni = 0; ni < 4; ni++) {
        int o = 8 * (4 * h + ni) + 2 * tc;
#pragma unroll
        for (int mi = 0; mi < 2; mi++) {
            int pr = 32 * g + mi * 16 + gr;
            out[ob + (size_t)o * HW + pr]           = acc[mi][ni][0];
            out[ob + (size_t)(o + 1) * HW + pr]     = acc[mi][ni][1];
            out[ob + (size_t)o * HW + pr + 8]       = acc[mi][ni][2];
            out[ob + (size_t)(o + 1) * HW + pr + 8] = acc[mi][ni][3];
        }
    }
}

// ---------------------------------------------------------------------------
extern "C" void kernel_launch(void* const* d_in, const int* in_sizes, int n_in,
                              void* d_out, int out_size)
{
    const float* x    = (const float*)d_in[0];
    const float* woff = (const float*)d_in[1];
    const float* boff = (const float*)d_in[2];
    const float* wdef = (const float*)d_in[3];
    const float* bdef = (const float*)d_in[4];
    float* out = (float*)d_out;

    wfrag_kernel<<<(9 * 8 * 8 * 32 + 255) / 256, 256>>>(wdef);
    wofrag_kernel<<<(72 * 3 * 32 + 255) / 256, 256>>>(woff);
    offset_mma_kernel<<<dim3(Ww / 128, Hh, Nn), 128>>>(x, boff);
    deform_mma_kernel<<<dim3(Ww / 64, Hh, Nn), 128>>>(x, bdef, out);
}